// round 15
// baseline (speedup 1.0000x reference)
#include <cuda_runtime.h>
#include <math.h>
#include <stdint.h>

#define OBS_C  128
#define MLPC   256
#define NGRIDC 16
#define NRC    64
#define NPC    128
#define NHC    64
#define GC     64
#define MC     7

#define XSTR   1792            // 7*256 floats per g
#define TWO_PI_F 6.2831853071795864f
#define PI_F     3.1415926535897932f

// ---------------- device scratch ----------------
__device__ __align__(16) float g_X[2][GC * XSTR];     // activations ping-pong
__device__ __align__(16) float g_coef[GC * 16 * MC];  // output-layer coeffs (g, o, m)
__device__ __align__(16) float g_sax[NHC * 4];        // ax table [h][k]
__device__ __align__(8)  float2 g_T1[NPC], g_T2[NPC], g_T3[NPC];  // phi harmonics

// ---------------- helpers ----------------
__device__ __forceinline__ float elu1(float x) { return x > 0.f ? x : expm1f(x); }

__device__ __forceinline__ void make_tables(int tid, float* sBc, float* sBs) {
    if (tid < NGRIDC) {
        float th = (float)tid * (TWO_PI_F / NGRIDC);
#pragma unroll
        for (int l = 0; l < 3; l++) {
            float s, c;
            sincosf((float)(l + 1) * th, &s, &c);
            sBc[tid * 3 + l] = c;
            sBs[tid * 3 + l] = s;
        }
    }
}

__device__ __forceinline__ void felu(
    float y0, const float yc[3], const float ys[3],
    const float* __restrict__ sBc, const float* __restrict__ sBs,
    float& z0, float zc[3], float zs[3])
{
    z0 = 0.f; zc[0] = zc[1] = zc[2] = 0.f; zs[0] = zs[1] = zs[2] = 0.f;
#pragma unroll
    for (int j = 0; j < NGRIDC; j++) {
        float c0 = sBc[j*3], c1v = sBc[j*3+1], c2v = sBc[j*3+2];
        float s0 = sBs[j*3], s1v = sBs[j*3+1], s2v = sBs[j*3+2];
        float v = y0 + yc[0]*c0 + yc[1]*c1v + yc[2]*c2v
                     + ys[0]*s0 + ys[1]*s1v + ys[2]*s2v;
        float w = elu1(v);
        z0 += w;
        zc[0] += w*c0; zc[1] += w*c1v; zc[2] += w*c2v;
        zs[0] += w*s0; zs[1] += w*s1v; zs[2] += w*s2v;
    }
    z0 *= (1.f/NGRIDC);
#pragma unroll
    for (int l = 0; l < 3; l++) { zc[l] *= (2.f/NGRIDC); zs[l] *= (2.f/NGRIDC); }
}

#define DOT4(acc, a, v) (acc) += (a).x*(v).x + (a).y*(v).y + (a).z*(v).z + (a).w*(v).w
#define CPLX4(accC, accS, a, b, vc, vs) \
    (accC) += (a).x*(vc).x - (b).x*(vs).x;  (accC) += (a).y*(vc).y - (b).y*(vs).y; \
    (accC) += (a).z*(vc).z - (b).z*(vs).z;  (accC) += (a).w*(vc).w - (b).w*(vs).w; \
    (accS) += (b).x*(vc).x + (a).x*(vs).x;  (accS) += (b).y*(vc).y + (a).y*(vs).y; \
    (accS) += (b).z*(vc).z + (a).z*(vs).z;  (accS) += (b).w*(vc).w + (a).w*(vs).w;

// ---------------- layer 1: matvec shared across actions + trig + coef init ----
// grid (32, 2): (o-tile of 8, b). 256 threads, warp -> 1 o.
__global__ __launch_bounds__(256, 1) void k_l1(
    const float* __restrict__ obs, const float* __restrict__ act,
    const float* __restrict__ W01, const float* __restrict__ b01,
    const float* __restrict__ AB1, const float* __restrict__ bout)
{
    const int tid = threadIdx.x, lane = tid & 31, wid = tid >> 5;
    const int bx = blockIdx.x, b = blockIdx.y;
    __shared__ float Xs[7 * 128];      // [comp][c]
    __shared__ float sY[8][7];
    __shared__ float sBc[48], sBs[48];

    // one block fills the expansion trig tables (read 3 launches later)
    if (bx == 0 && b == 0) {
        int h = tid >> 2, k = tid & 3;
        g_sax[tid] = 1.4142135623730951f *
                     sinf((float)(k + 1) * PI_F * (float)h * (1.f / (NHC - 1)));
        if (tid < NPC) {
            float phi = (float)tid * (TWO_PI_F / NPC);
            float s1, c1v;
            sincosf(phi, &s1, &c1v);
            float c2v = c1v*c1v - s1*s1;
            float s2  = 2.f*s1*c1v;
            float c3v = c2v*c1v - s2*s1;
            float s3  = s2*c1v + c2v*s1;
            g_T1[tid] = make_float2(c1v, s1);
            g_T2[tid] = make_float2(c2v, s2);
            g_T3[tid] = make_float2(c3v, s3);
        }
    }

    // initialize g_coef for this block's g: bias in m=0, zeros elsewhere.
    // (hidden layer 2 atomically accumulates the output layer into this.)
    {
        const int g = b * 32 + bx;   // bijection over 0..63
        if (tid < 112) {
            const int out = tid / 7, m = tid - 7 * out;
            g_coef[(size_t)g * 112 + tid] = (m == 0) ? bout[out] : 0.f;
        }
    }

    const int o = bx * 8 + wid;

    const float* w0r = W01 + (size_t)o * (OBS_C + 1) + 4 * lane;
    float w0x = w0r[0], w0y = w0r[1], w0z = w0r[2], w0w = w0r[3];
    float4 wa[3], wb[3];
#pragma unroll
    for (int l = 0; l < 3; l++) {
        wa[l] = ((const float4*)AB1)[((size_t)(2*l)*256 + o)*32 + lane];
        wb[l] = ((const float4*)AB1)[((size_t)(2*l+1)*256 + o)*32 + lane];
    }

    const float* orow = obs + (size_t)b * (OBS_C * MC);
    for (int idx = tid; idx < OBS_C * MC; idx += 256) {
        int c = idx / 7, t = idx - c * 7;
        Xs[t * 128 + c] = orow[idx];
    }
    make_tables(tid, sBc, sBs);
    __syncthreads();

    const float4* Xs4 = (const float4*)Xs;
    {
        float acc[7];
#pragma unroll
        for (int m = 0; m < 7; m++) acc[m] = 0.f;
        float4 v0 = Xs4[lane];
        acc[0] += w0x*v0.x + w0y*v0.y + w0z*v0.z + w0w*v0.w;
#pragma unroll
        for (int l = 0; l < 3; l++) {
            float4 vc = Xs4[(1 + 2*l)*32 + lane];
            float4 vs = Xs4[(2 + 2*l)*32 + lane];
            CPLX4(acc[1+2*l], acc[2+2*l], wa[l], wb[l], vc, vs);
        }
#pragma unroll
        for (int off = 16; off > 0; off >>= 1)
#pragma unroll
            for (int m = 0; m < 7; m++)
                acc[m] += __shfl_xor_sync(0xffffffffu, acc[m], off);
        if (lane == 0)
#pragma unroll
            for (int m = 0; m < 7; m++) sY[wid][m] = acc[m];
    }
    __syncthreads();

    {
        const int a = tid >> 3, ol = tid & 7;
        const int oo = bx * 8 + ol;
        const int g = b * 32 + a;
        float y0 = sY[ol][0] + b01[oo] + W01[(size_t)oo * 129 + 128] * act[g];
        float yc[3], ys[3];
#pragma unroll
        for (int l = 0; l < 3; l++) { yc[l] = sY[ol][1+2*l]; ys[l] = sY[ol][2+2*l]; }
        float z0, zc[3], zs[3];
        felu(y0, yc, ys, sBc, sBs, z0, zc, zs);
        float* xo = g_X[0] + (size_t)g * XSTR;
        xo[oo] = z0;
#pragma unroll
        for (int l = 0; l < 3; l++) {
            xo[(1+2*l)*256 + oo] = zc[l];
            xo[(2+2*l)*256 + oo] = zs[l];
        }
    }
}

// ---------------- hidden layer: 2 CTA/SM, one wave; layer 2 fuses output layer -
// grid (16, 16): (o-tile of 16, g-tile of 4). warp -> 2 o's x 4 g's.
__global__ __launch_bounds__(256, 2) void k_hidden(
    const float* __restrict__ W0h, const float* __restrict__ b0h,
    const float* __restrict__ ABh,
    const float* __restrict__ Wout, const float* __restrict__ ABout,
    int layer, int inb, int fuse_out)
{
    const int tid = threadIdx.x, lane = tid & 31, wid = tid >> 5;
    const int bx = blockIdx.x, gt = blockIdx.y;
    __shared__ __align__(16) float Xs[4 * XSTR];   // 28 KB
    __shared__ float sY[16][4][7];
    __shared__ float zbuf[4][7][16];               // post-felu z, layer-2 only
    __shared__ float sBc[48], sBs[48];

    const float4* W04 = (const float4*)(W0h + (size_t)layer * 65536);
    const float4* AB4 = (const float4*)(ABh + (size_t)layer * 393216);
    const int oA = bx * 16 + wid * 2;
    const int oB = oA + 1;

    // j=0 weight set prefetched before staging sync (overlaps)
    float4 w[14];
    {
        const int i4 = lane;
        w[0] = W04[(size_t)oA * 64 + i4];
        w[1] = W04[(size_t)oB * 64 + i4];
#pragma unroll
        for (int l = 0; l < 3; l++) {
            w[2 + 4*l + 0] = AB4[((size_t)(2*l)*256   + oA)*64 + i4];
            w[2 + 4*l + 1] = AB4[((size_t)(2*l+1)*256 + oA)*64 + i4];
            w[2 + 4*l + 2] = AB4[((size_t)(2*l)*256   + oB)*64 + i4];
            w[2 + 4*l + 3] = AB4[((size_t)(2*l+1)*256 + oB)*64 + i4];
        }
    }

    {
        const float4* src = (const float4*)(g_X[inb] + (size_t)gt * 4 * XSTR);
        float4* dst = (float4*)Xs;
#pragma unroll
        for (int i = tid; i < 4 * XSTR / 4; i += 256) dst[i] = src[i];
    }
    make_tables(tid, sBc, sBs);
    __syncthreads();

    const float4* Xs4 = (const float4*)Xs;
    float acc[2][4][7];
#pragma unroll
    for (int t = 0; t < 2; t++)
#pragma unroll
        for (int g = 0; g < 4; g++)
#pragma unroll
            for (int m = 0; m < 7; m++) acc[t][g][m] = 0.f;

#pragma unroll 1
    for (int j = 0; j < 2; j++) {
        const int i4 = lane + 32 * j;
        if (j == 1) {
            w[0] = W04[(size_t)oA * 64 + i4];
            w[1] = W04[(size_t)oB * 64 + i4];
#pragma unroll
            for (int l = 0; l < 3; l++) {
                w[2 + 4*l + 0] = AB4[((size_t)(2*l)*256   + oA)*64 + i4];
                w[2 + 4*l + 1] = AB4[((size_t)(2*l+1)*256 + oA)*64 + i4];
                w[2 + 4*l + 2] = AB4[((size_t)(2*l)*256   + oB)*64 + i4];
                w[2 + 4*l + 3] = AB4[((size_t)(2*l+1)*256 + oB)*64 + i4];
            }
        }
#pragma unroll
        for (int g = 0; g < 4; g++) {
            const int base = g * (XSTR/4);
            float4 v0 = Xs4[base + i4];
            DOT4(acc[0][g][0], w[0], v0);
            DOT4(acc[1][g][0], w[1], v0);
#pragma unroll
            for (int l = 0; l < 3; l++) {
                float4 vc = Xs4[base + (1+2*l)*64 + i4];
                float4 vs = Xs4[base + (2+2*l)*64 + i4];
                CPLX4(acc[0][g][1+2*l], acc[0][g][2+2*l], w[2+4*l+0], w[2+4*l+1], vc, vs);
                CPLX4(acc[1][g][1+2*l], acc[1][g][2+2*l], w[2+4*l+2], w[2+4*l+3], vc, vs);
            }
        }
    }
#pragma unroll
    for (int off = 16; off > 0; off >>= 1)
#pragma unroll
        for (int t = 0; t < 2; t++)
#pragma unroll
            for (int g = 0; g < 4; g++)
#pragma unroll
                for (int m = 0; m < 7; m++)
                    acc[t][g][m] += __shfl_xor_sync(0xffffffffu, acc[t][g][m], off);
    if (lane == 0)
#pragma unroll
        for (int t = 0; t < 2; t++)
#pragma unroll
            for (int g = 0; g < 4; g++)
#pragma unroll
                for (int m = 0; m < 7; m++) sY[wid*2 + t][g][m] = acc[t][g][m];
    __syncthreads();

    // epilogue: felu for 16 o x 4 g
    if (tid < 64) {
        const int gl = tid >> 4, ol = tid & 15;
        const int o = bx * 16 + ol;
        const int g = gt * 4 + gl;
        float y0 = sY[ol][gl][0] + b0h[layer * 256 + o];
        float yc[3], ys[3];
#pragma unroll
        for (int l = 0; l < 3; l++) { yc[l] = sY[ol][gl][1+2*l]; ys[l] = sY[ol][gl][2+2*l]; }
        float z0, zc[3], zs[3];
        felu(y0, yc, ys, sBc, sBs, z0, zc, zs);
        if (!fuse_out) {
            float* xo = g_X[inb ^ 1] + (size_t)g * XSTR;
            xo[o] = z0;
#pragma unroll
            for (int l = 0; l < 3; l++) {
                xo[(1+2*l)*256 + o] = zc[l];
                xo[(2+2*l)*256 + o] = zs[l];
            }
        } else {
            zbuf[gl][0][ol] = z0;
#pragma unroll
            for (int l = 0; l < 3; l++) {
                zbuf[gl][1+2*l][ol] = zc[l];
                zbuf[gl][2+2*l][ol] = zs[l];
            }
        }
    }

    // fused output layer: partial contraction over this block's 16 channels,
    // accumulated atomically into g_coef (bias pre-loaded by k_l1).
    if (fuse_out) {
        __syncthreads();
        const int chBase = bx * 16;
#pragma unroll 1
        for (int idx = tid; idx < 448; idx += 256) {
            const int gl = idx / 112;
            const int rem = idx - gl * 112;
            const int out = rem / 7, m = rem - out * 7;
            float s = 0.f;
            if (m == 0) {
                const float* wr = Wout + (size_t)out * 256 + chBase;
                const float* zb = zbuf[gl][0];
#pragma unroll
                for (int i = 0; i < 16; i++) s += wr[i] * zb[i];
            } else {
                const int l = (m - 1) >> 1;
                const int isSin = (m - 1) & 1;   // 0: cos-row, 1: sin-row
                const float* ar = ABout + ((size_t)(2*l)  *16 + out) * 256 + chBase;
                const float* br = ABout + ((size_t)(2*l+1)*16 + out) * 256 + chBase;
                const float* zcb = zbuf[gl][1+2*l];
                const float* zsb = zbuf[gl][2+2*l];
                if (!isSin) {
#pragma unroll
                    for (int i = 0; i < 16; i++) s += ar[i]*zcb[i] - br[i]*zsb[i];
                } else {
#pragma unroll
                    for (int i = 0; i < 16; i++) s += br[i]*zcb[i] + ar[i]*zsb[i];
                }
            }
            const int g = gt * 4 + gl;
            atomicAdd(&g_coef[(size_t)g * 112 + out * 7 + m], s);
        }
    }
}

// ---------------- expansion kernel: table-driven prologue, __stcs stores -------
__global__ __launch_bounds__(256) void k_expand(
    const float* __restrict__ rad, float* __restrict__ out)
{
    const int gr = blockIdx.x;          // g*NR + r
    const int tid = threadIdx.x;
    __shared__ float sc1[28];
    __shared__ float su[NPC * 4];       // [p][k] -> float4 per p

    if (tid < 28) {
        const int g = gr >> 6, r = gr & 63;
        const int k = tid / 7, m = tid - 7 * k;
        const float* cf = g_coef + (size_t)g * 112;
        float s = 0.f;
#pragma unroll
        for (int n = 0; n < 4; n++)
            s += cf[(n*4 + k)*7 + m] * rad[(m*4 + n) * NRC + r];
        sc1[tid] = s;
    }

    const int hgrp = tid & 15;
    float4 axj[4];
#pragma unroll
    for (int j = 0; j < 4; j++)
        axj[j] = ((const float4*)g_sax)[hgrp * 4 + j];
    __syncthreads();

    const float A0 = 0.3989422804014327f;   // 1/sqrt(2*pi)
    const float ISP = 0.5641895835477563f;  // 1/sqrt(pi)
#pragma unroll
    for (int idx = tid; idx < 512; idx += 256) {
        int k = idx >> 7, p = idx & 127;
        float2 t1 = g_T1[p], t2 = g_T2[p], t3 = g_T3[p];
        const float* c = sc1 + k * MC;
        su[p * 4 + k] = c[0]*A0 + ISP*(c[1]*t1.x + c[2]*t1.y +
                                       c[3]*t2.x + c[4]*t2.y +
                                       c[5]*t3.x + c[6]*t3.y);
    }
    __syncthreads();

    const float4* su4 = (const float4*)su;
    float4* ob = (float4*)out + (size_t)gr * (NPC * NHC / 4);
    const int pg = tid >> 4;
#pragma unroll
    for (int it = 0; it < 8; it++) {
        int p = it * 16 + pg;
        float4 u = su4[p];
        float4 v;
        v.x = u.x*axj[0].x + u.y*axj[0].y + u.z*axj[0].z + u.w*axj[0].w;
        v.y = u.x*axj[1].x + u.y*axj[1].y + u.z*axj[1].z + u.w*axj[1].w;
        v.z = u.x*axj[2].x + u.y*axj[2].y + u.z*axj[2].z + u.w*axj[2].w;
        v.w = u.x*axj[3].x + u.y*axj[3].y + u.z*axj[3].z + u.w*axj[3].w;
        __stcs(&ob[p * 16 + hgrp], v);
    }
}

// ---------------- launch ----------------
extern "C" void kernel_launch(void* const* d_in, const int* in_sizes, int n_in,
                              void* d_out, int out_size)
{
    const float* obs   = (const float*)d_in[0];
    const float* act   = (const float*)d_in[1];
    const float* W0_1  = (const float*)d_in[2];
    const float* b0_1  = (const float*)d_in[3];
    const float* AB1   = (const float*)d_in[4];
    const float* W0_h  = (const float*)d_in[5];
    const float* b0_h  = (const float*)d_in[6];
    const float* ABh   = (const float*)d_in[7];
    const float* Wout0 = (const float*)d_in[8];
    const float* bout0 = (const float*)d_in[9];
    const float* ABout = (const float*)d_in[10];
    const float* rad   = (const float*)d_in[11];

    k_l1<<<dim3(32, 2), 256>>>(obs, act, W0_1, b0_1, AB1, bout0);
    k_hidden<<<dim3(16, 16), 256>>>(W0_h, b0_h, ABh, Wout0, ABout, 0, 0, 0);
    k_hidden<<<dim3(16, 16), 256>>>(W0_h, b0_h, ABh, Wout0, ABout, 1, 1, 1);
    k_expand<<<GC * NRC, 256>>>(rad, (float*)d_out);
}

// round 16
// speedup vs baseline: 1.1725x; 1.1725x over previous
#include <cuda_runtime.h>
#include <math.h>
#include <stdint.h>

#define OBS_C  128
#define MLPC   256
#define NGRIDC 16
#define NRC    64
#define NPC    128
#define NHC    64
#define GC     64
#define MC     7

#define XSTR   1792            // 7*256 floats per g
#define TWO_PI_F 6.2831853071795864f
#define PI_F     3.1415926535897932f

// ---------------- device scratch ----------------
__device__ __align__(16) float g_X[2][GC * XSTR];     // activations ping-pong
__device__ __align__(16) float g_coef[GC * 16 * MC];  // output-layer coeffs (g, o, m)
__device__ __align__(16) float g_sax[NHC * 4];        // ax table [h][k]
__device__ __align__(8)  float2 g_T1[NPC], g_T2[NPC], g_T3[NPC];  // phi harmonics

// ---------------- helpers ----------------
__device__ __forceinline__ float elu1(float x) { return x > 0.f ? x : expm1f(x); }

__device__ __forceinline__ void make_tables(int tid, float* sBc, float* sBs) {
    if (tid < NGRIDC) {
        float th = (float)tid * (TWO_PI_F / NGRIDC);
#pragma unroll
        for (int l = 0; l < 3; l++) {
            float s, c;
            sincosf((float)(l + 1) * th, &s, &c);
            sBc[tid * 3 + l] = c;
            sBs[tid * 3 + l] = s;
        }
    }
}

__device__ __forceinline__ void felu(
    float y0, const float yc[3], const float ys[3],
    const float* __restrict__ sBc, const float* __restrict__ sBs,
    float& z0, float zc[3], float zs[3])
{
    z0 = 0.f; zc[0] = zc[1] = zc[2] = 0.f; zs[0] = zs[1] = zs[2] = 0.f;
#pragma unroll
    for (int j = 0; j < NGRIDC; j++) {
        float c0 = sBc[j*3], c1v = sBc[j*3+1], c2v = sBc[j*3+2];
        float s0 = sBs[j*3], s1v = sBs[j*3+1], s2v = sBs[j*3+2];
        float v = y0 + yc[0]*c0 + yc[1]*c1v + yc[2]*c2v
                     + ys[0]*s0 + ys[1]*s1v + ys[2]*s2v;
        float w = elu1(v);
        z0 += w;
        zc[0] += w*c0; zc[1] += w*c1v; zc[2] += w*c2v;
        zs[0] += w*s0; zs[1] += w*s1v; zs[2] += w*s2v;
    }
    z0 *= (1.f/NGRIDC);
#pragma unroll
    for (int l = 0; l < 3; l++) { zc[l] *= (2.f/NGRIDC); zs[l] *= (2.f/NGRIDC); }
}

#define DOT4(acc, a, v) (acc) += (a).x*(v).x + (a).y*(v).y + (a).z*(v).z + (a).w*(v).w
#define CPLX4(accC, accS, a, b, vc, vs) \
    (accC) += (a).x*(vc).x - (b).x*(vs).x;  (accC) += (a).y*(vc).y - (b).y*(vs).y; \
    (accC) += (a).z*(vc).z - (b).z*(vs).z;  (accC) += (a).w*(vc).w - (b).w*(vs).w; \
    (accS) += (b).x*(vc).x + (a).x*(vs).x;  (accS) += (b).y*(vc).y + (a).y*(vs).y; \
    (accS) += (b).z*(vc).z + (a).z*(vs).z;  (accS) += (b).w*(vc).w + (a).w*(vs).w;

// ---------------- layer 1: matvec shared across actions + trig precompute -----
// grid (32, 2): (o-tile of 8, b). 256 threads, warp -> 1 o.
__global__ __launch_bounds__(256, 1) void k_l1(
    const float* __restrict__ obs, const float* __restrict__ act,
    const float* __restrict__ W01, const float* __restrict__ b01,
    const float* __restrict__ AB1)
{
    const int tid = threadIdx.x, lane = tid & 31, wid = tid >> 5;
    const int bx = blockIdx.x, b = blockIdx.y;
    __shared__ float Xs[7 * 128];      // [comp][c]
    __shared__ float sY[8][7];
    __shared__ float sBc[48], sBs[48];

    // one block fills the expansion trig tables (read 3 launches later)
    if (bx == 0 && b == 0) {
        int h = tid >> 2, k = tid & 3;
        g_sax[tid] = 1.4142135623730951f *
                     sinf((float)(k + 1) * PI_F * (float)h * (1.f / (NHC - 1)));
        if (tid < NPC) {
            float phi = (float)tid * (TWO_PI_F / NPC);
            float s1, c1v;
            sincosf(phi, &s1, &c1v);
            float c2v = c1v*c1v - s1*s1;
            float s2  = 2.f*s1*c1v;
            float c3v = c2v*c1v - s2*s1;
            float s3  = s2*c1v + c2v*s1;
            g_T1[tid] = make_float2(c1v, s1);
            g_T2[tid] = make_float2(c2v, s2);
            g_T3[tid] = make_float2(c3v, s3);
        }
    }

    const int o = bx * 8 + wid;

    const float* w0r = W01 + (size_t)o * (OBS_C + 1) + 4 * lane;
    float w0x = w0r[0], w0y = w0r[1], w0z = w0r[2], w0w = w0r[3];
    float4 wa[3], wb[3];
#pragma unroll
    for (int l = 0; l < 3; l++) {
        wa[l] = ((const float4*)AB1)[((size_t)(2*l)*256 + o)*32 + lane];
        wb[l] = ((const float4*)AB1)[((size_t)(2*l+1)*256 + o)*32 + lane];
    }

    const float* orow = obs + (size_t)b * (OBS_C * MC);
    for (int idx = tid; idx < OBS_C * MC; idx += 256) {
        int c = idx / 7, t = idx - c * 7;
        Xs[t * 128 + c] = orow[idx];
    }
    make_tables(tid, sBc, sBs);
    __syncthreads();

    const float4* Xs4 = (const float4*)Xs;
    {
        float acc[7];
#pragma unroll
        for (int m = 0; m < 7; m++) acc[m] = 0.f;
        float4 v0 = Xs4[lane];
        acc[0] += w0x*v0.x + w0y*v0.y + w0z*v0.z + w0w*v0.w;
#pragma unroll
        for (int l = 0; l < 3; l++) {
            float4 vc = Xs4[(1 + 2*l)*32 + lane];
            float4 vs = Xs4[(2 + 2*l)*32 + lane];
            CPLX4(acc[1+2*l], acc[2+2*l], wa[l], wb[l], vc, vs);
        }
#pragma unroll
        for (int off = 16; off > 0; off >>= 1)
#pragma unroll
            for (int m = 0; m < 7; m++)
                acc[m] += __shfl_xor_sync(0xffffffffu, acc[m], off);
        if (lane == 0)
#pragma unroll
            for (int m = 0; m < 7; m++) sY[wid][m] = acc[m];
    }
    __syncthreads();

    {
        const int a = tid >> 3, ol = tid & 7;
        const int oo = bx * 8 + ol;
        const int g = b * 32 + a;
        float y0 = sY[ol][0] + b01[oo] + W01[(size_t)oo * 129 + 128] * act[g];
        float yc[3], ys[3];
#pragma unroll
        for (int l = 0; l < 3; l++) { yc[l] = sY[ol][1+2*l]; ys[l] = sY[ol][2+2*l]; }
        float z0, zc[3], zs[3];
        felu(y0, yc, ys, sBc, sBs, z0, zc, zs);
        float* xo = g_X[0] + (size_t)g * XSTR;
        xo[oo] = z0;
#pragma unroll
        for (int l = 0; l < 3; l++) {
            xo[(1+2*l)*256 + oo] = zc[l];
            xo[(2+2*l)*256 + oo] = zs[l];
        }
    }
}

// ---------------- hidden layer: 2 CTA/SM, one wave -----------------------------
// grid (16, 16): (o-tile of 16, g-tile of 4). warp -> 2 o's x 4 g's.
__global__ __launch_bounds__(256, 2) void k_hidden(
    const float* __restrict__ W0h, const float* __restrict__ b0h,
    const float* __restrict__ ABh, int layer, int inb)
{
    const int tid = threadIdx.x, lane = tid & 31, wid = tid >> 5;
    const int bx = blockIdx.x, gt = blockIdx.y;
    __shared__ __align__(16) float Xs[4 * XSTR];   // 28 KB
    __shared__ float sY[16][4][7];
    __shared__ float sBc[48], sBs[48];

    const float4* W04 = (const float4*)(W0h + (size_t)layer * 65536);
    const float4* AB4 = (const float4*)(ABh + (size_t)layer * 393216);
    const int oA = bx * 16 + wid * 2;
    const int oB = oA + 1;

    // j=0 weight set prefetched before staging sync (overlaps)
    float4 w[14];
    {
        const int i4 = lane;
        w[0] = W04[(size_t)oA * 64 + i4];
        w[1] = W04[(size_t)oB * 64 + i4];
#pragma unroll
        for (int l = 0; l < 3; l++) {
            w[2 + 4*l + 0] = AB4[((size_t)(2*l)*256   + oA)*64 + i4];
            w[2 + 4*l + 1] = AB4[((size_t)(2*l+1)*256 + oA)*64 + i4];
            w[2 + 4*l + 2] = AB4[((size_t)(2*l)*256   + oB)*64 + i4];
            w[2 + 4*l + 3] = AB4[((size_t)(2*l+1)*256 + oB)*64 + i4];
        }
    }

    {
        const float4* src = (const float4*)(g_X[inb] + (size_t)gt * 4 * XSTR);
        float4* dst = (float4*)Xs;
#pragma unroll
        for (int i = tid; i < 4 * XSTR / 4; i += 256) dst[i] = src[i];
    }
    make_tables(tid, sBc, sBs);
    __syncthreads();

    const float4* Xs4 = (const float4*)Xs;
    float acc[2][4][7];
#pragma unroll
    for (int t = 0; t < 2; t++)
#pragma unroll
        for (int g = 0; g < 4; g++)
#pragma unroll
            for (int m = 0; m < 7; m++) acc[t][g][m] = 0.f;

#pragma unroll 1
    for (int j = 0; j < 2; j++) {
        const int i4 = lane + 32 * j;
        if (j == 1) {
            w[0] = W04[(size_t)oA * 64 + i4];
            w[1] = W04[(size_t)oB * 64 + i4];
#pragma unroll
            for (int l = 0; l < 3; l++) {
                w[2 + 4*l + 0] = AB4[((size_t)(2*l)*256   + oA)*64 + i4];
                w[2 + 4*l + 1] = AB4[((size_t)(2*l+1)*256 + oA)*64 + i4];
                w[2 + 4*l + 2] = AB4[((size_t)(2*l)*256   + oB)*64 + i4];
                w[2 + 4*l + 3] = AB4[((size_t)(2*l+1)*256 + oB)*64 + i4];
            }
        }
#pragma unroll
        for (int g = 0; g < 4; g++) {
            const int base = g * (XSTR/4);
            float4 v0 = Xs4[base + i4];
            DOT4(acc[0][g][0], w[0], v0);
            DOT4(acc[1][g][0], w[1], v0);
#pragma unroll
            for (int l = 0; l < 3; l++) {
                float4 vc = Xs4[base + (1+2*l)*64 + i4];
                float4 vs = Xs4[base + (2+2*l)*64 + i4];
                CPLX4(acc[0][g][1+2*l], acc[0][g][2+2*l], w[2+4*l+0], w[2+4*l+1], vc, vs);
                CPLX4(acc[1][g][1+2*l], acc[1][g][2+2*l], w[2+4*l+2], w[2+4*l+3], vc, vs);
            }
        }
    }
#pragma unroll
    for (int off = 16; off > 0; off >>= 1)
#pragma unroll
        for (int t = 0; t < 2; t++)
#pragma unroll
            for (int g = 0; g < 4; g++)
#pragma unroll
                for (int m = 0; m < 7; m++)
                    acc[t][g][m] += __shfl_xor_sync(0xffffffffu, acc[t][g][m], off);
    if (lane == 0)
#pragma unroll
        for (int t = 0; t < 2; t++)
#pragma unroll
            for (int g = 0; g < 4; g++)
#pragma unroll
                for (int m = 0; m < 7; m++) sY[wid*2 + t][g][m] = acc[t][g][m];
    __syncthreads();

    if (tid < 64) {
        const int gl = tid >> 4, ol = tid & 15;
        const int o = bx * 16 + ol;
        const int g = gt * 4 + gl;
        float y0 = sY[ol][gl][0] + b0h[layer * 256 + o];
        float yc[3], ys[3];
#pragma unroll
        for (int l = 0; l < 3; l++) { yc[l] = sY[ol][gl][1+2*l]; ys[l] = sY[ol][gl][2+2*l]; }
        float z0, zc[3], zs[3];
        felu(y0, yc, ys, sBc, sBs, z0, zc, zs);
        float* xo = g_X[inb ^ 1] + (size_t)g * XSTR;
        xo[o] = z0;
#pragma unroll
        for (int l = 0; l < 3; l++) {
            xo[(1+2*l)*256 + o] = zc[l];
            xo[(2+2*l)*256 + o] = zs[l];
        }
    }
}

// ---------------- output layer: grid (64,2), warp-per-o, all loads batched -----
__global__ __launch_bounds__(256, 1) void k_out(
    const float* __restrict__ Wout, const float* __restrict__ bout,
    const float* __restrict__ ABout, int inb)
{
    const int tid = threadIdx.x, lane = tid & 31, wid = tid >> 5;
    const int g = blockIdx.x, half = blockIdx.y;
    const int o = half * 8 + wid;
    const float4* Xg = (const float4*)(g_X[inb] + (size_t)g * XSTR);

    float4 w[2][7], xv[2][7];
#pragma unroll
    for (int j = 0; j < 2; j++) {
        const int i4 = lane + 32 * j;
        w[j][0] = ((const float4*)Wout)[(size_t)o * 64 + i4];
#pragma unroll
        for (int l = 0; l < 3; l++) {
            w[j][1 + 2*l] = ((const float4*)ABout)[((size_t)(2*l)*16 + o)*64 + i4];
            w[j][2 + 2*l] = ((const float4*)ABout)[((size_t)(2*l+1)*16 + o)*64 + i4];
        }
        xv[j][0] = Xg[i4];
#pragma unroll
        for (int l = 0; l < 3; l++) {
            xv[j][1 + 2*l] = Xg[(1+2*l)*64 + i4];
            xv[j][2 + 2*l] = Xg[(2+2*l)*64 + i4];
        }
    }

    float acc[7];
#pragma unroll
    for (int m = 0; m < 7; m++) acc[m] = 0.f;
#pragma unroll
    for (int j = 0; j < 2; j++) {
        DOT4(acc[0], w[j][0], xv[j][0]);
#pragma unroll
        for (int l = 0; l < 3; l++) {
            CPLX4(acc[1+2*l], acc[2+2*l], w[j][1+2*l], w[j][2+2*l], xv[j][1+2*l], xv[j][2+2*l]);
        }
    }
#pragma unroll
    for (int off = 16; off > 0; off >>= 1)
#pragma unroll
        for (int m = 0; m < 7; m++)
            acc[m] += __shfl_xor_sync(0xffffffffu, acc[m], off);
    if (lane == 0) {
        float* dst = g_coef + ((size_t)g * 16 + o) * MC;
        dst[0] = acc[0] + bout[o];
#pragma unroll
        for (int m = 1; m < 7; m++) dst[m] = acc[m];
    }
}

// ---------------- expansion kernel: table-driven, forced 32 regs / 8 blk/SM ----
__global__ __launch_bounds__(256, 8) void k_expand(
    const float* __restrict__ rad, float* __restrict__ out)
{
    const int gr = blockIdx.x;          // g*NR + r
    const int tid = threadIdx.x;
    __shared__ float sc1[28];
    __shared__ float su[NPC * 4];       // [p][k] -> float4 per p

    if (tid < 28) {
        const int g = gr >> 6, r = gr & 63;
        const int k = tid / 7, m = tid - 7 * k;
        const float* cf = g_coef + (size_t)g * 112;
        float s = 0.f;
#pragma unroll
        for (int n = 0; n < 4; n++)
            s += cf[(n*4 + k)*7 + m] * rad[(m*4 + n) * NRC + r];
        sc1[tid] = s;
    }

    const int hgrp = tid & 15;
    float4 axj[4];
#pragma unroll
    for (int j = 0; j < 4; j++)
        axj[j] = ((const float4*)g_sax)[hgrp * 4 + j];
    __syncthreads();

    const float A0 = 0.3989422804014327f;   // 1/sqrt(2*pi)
    const float ISP = 0.5641895835477563f;  // 1/sqrt(pi)
#pragma unroll
    for (int idx = tid; idx < 512; idx += 256) {
        int k = idx >> 7, p = idx & 127;
        float2 t1 = g_T1[p], t2 = g_T2[p], t3 = g_T3[p];
        const float* c = sc1 + k * MC;
        su[p * 4 + k] = c[0]*A0 + ISP*(c[1]*t1.x + c[2]*t1.y +
                                       c[3]*t2.x + c[4]*t2.y +
                                       c[5]*t3.x + c[6]*t3.y);
    }
    __syncthreads();

    const float4* su4 = (const float4*)su;
    float4* ob = (float4*)out + (size_t)gr * (NPC * NHC / 4);
    const int pg = tid >> 4;
#pragma unroll
    for (int it = 0; it < 8; it++) {
        int p = it * 16 + pg;
        float4 u = su4[p];
        float4 v;
        v.x = u.x*axj[0].x + u.y*axj[0].y + u.z*axj[0].z + u.w*axj[0].w;
        v.y = u.x*axj[1].x + u.y*axj[1].y + u.z*axj[1].z + u.w*axj[1].w;
        v.z = u.x*axj[2].x + u.y*axj[2].y + u.z*axj[2].z + u.w*axj[2].w;
        v.w = u.x*axj[3].x + u.y*axj[3].y + u.z*axj[3].z + u.w*axj[3].w;
        __stcs(&ob[p * 16 + hgrp], v);
    }
}

// ---------------- launch ----------------
extern "C" void kernel_launch(void* const* d_in, const int* in_sizes, int n_in,
                              void* d_out, int out_size)
{
    const float* obs   = (const float*)d_in[0];
    const float* act   = (const float*)d_in[1];
    const float* W0_1  = (const float*)d_in[2];
    const float* b0_1  = (const float*)d_in[3];
    const float* AB1   = (const float*)d_in[4];
    const float* W0_h  = (const float*)d_in[5];
    const float* b0_h  = (const float*)d_in[6];
    const float* ABh   = (const float*)d_in[7];
    const float* Wout0 = (const float*)d_in[8];
    const float* bout0 = (const float*)d_in[9];
    const float* ABout = (const float*)d_in[10];
    const float* rad   = (const float*)d_in[11];

    k_l1<<<dim3(32, 2), 256>>>(obs, act, W0_1, b0_1, AB1);
    k_hidden<<<dim3(16, 16), 256>>>(W0_h, b0_h, ABh, 0, 0);
    k_hidden<<<dim3(16, 16), 256>>>(W0_h, b0_h, ABh, 1, 1);
    k_out<<<dim3(64, 2), 256>>>(Wout0, bout0, ABout, 0);
    k_expand<<<GC * NRC, 256>>>(rad, (float*)d_out);
}

// round 17
// speedup vs baseline: 1.2565x; 1.0716x over previous
#include <cuda_runtime.h>
#include <math.h>
#include <stdint.h>

#define OBS_C  128
#define MLPC   256
#define NGRIDC 16
#define NRC    64
#define NPC    128
#define NHC    64
#define GC     64
#define MC     7

#define XSTR   1792            // 7*256 floats per g
#define TWO_PI_F 6.2831853071795864f
#define PI_F     3.1415926535897932f

// ---------------- device scratch ----------------
__device__ __align__(16) float g_X[2][GC * XSTR];     // activations ping-pong
__device__ __align__(16) float g_coef[GC * 16 * MC];  // output-layer coeffs (g, o, m)
__device__ __align__(16) float g_sax[NHC * 4];        // ax table [h][k]
__device__ __align__(8)  float2 g_T1[NPC], g_T2[NPC], g_T3[NPC];  // phi harmonics

// ---------------- PDL helpers ----------------
__device__ __forceinline__ void gdep_wait()   { asm volatile("griddepcontrol.wait;" ::: "memory"); }
__device__ __forceinline__ void gdep_launch() { asm volatile("griddepcontrol.launch_dependents;"); }

// ---------------- helpers ----------------
__device__ __forceinline__ float elu1(float x) { return x > 0.f ? x : expm1f(x); }

__device__ __forceinline__ void make_tables(int tid, float* sBc, float* sBs) {
    if (tid < NGRIDC) {
        float th = (float)tid * (TWO_PI_F / NGRIDC);
#pragma unroll
        for (int l = 0; l < 3; l++) {
            float s, c;
            sincosf((float)(l + 1) * th, &s, &c);
            sBc[tid * 3 + l] = c;
            sBs[tid * 3 + l] = s;
        }
    }
}

__device__ __forceinline__ void felu(
    float y0, const float yc[3], const float ys[3],
    const float* __restrict__ sBc, const float* __restrict__ sBs,
    float& z0, float zc[3], float zs[3])
{
    z0 = 0.f; zc[0] = zc[1] = zc[2] = 0.f; zs[0] = zs[1] = zs[2] = 0.f;
#pragma unroll
    for (int j = 0; j < NGRIDC; j++) {
        float c0 = sBc[j*3], c1v = sBc[j*3+1], c2v = sBc[j*3+2];
        float s0 = sBs[j*3], s1v = sBs[j*3+1], s2v = sBs[j*3+2];
        float v = y0 + yc[0]*c0 + yc[1]*c1v + yc[2]*c2v
                     + ys[0]*s0 + ys[1]*s1v + ys[2]*s2v;
        float w = elu1(v);
        z0 += w;
        zc[0] += w*c0; zc[1] += w*c1v; zc[2] += w*c2v;
        zs[0] += w*s0; zs[1] += w*s1v; zs[2] += w*s2v;
    }
    z0 *= (1.f/NGRIDC);
#pragma unroll
    for (int l = 0; l < 3; l++) { zc[l] *= (2.f/NGRIDC); zs[l] *= (2.f/NGRIDC); }
}

#define DOT4(acc, a, v) (acc) += (a).x*(v).x + (a).y*(v).y + (a).z*(v).z + (a).w*(v).w
#define CPLX4(accC, accS, a, b, vc, vs) \
    (accC) += (a).x*(vc).x - (b).x*(vs).x;  (accC) += (a).y*(vc).y - (b).y*(vs).y; \
    (accC) += (a).z*(vc).z - (b).z*(vs).z;  (accC) += (a).w*(vc).w - (b).w*(vs).w; \
    (accS) += (b).x*(vc).x + (a).x*(vs).x;  (accS) += (b).y*(vc).y + (a).y*(vs).y; \
    (accS) += (b).z*(vc).z + (a).z*(vs).z;  (accS) += (b).w*(vc).w + (a).w*(vs).w;

// ---------------- layer 1: matvec shared across actions + trig precompute -----
__global__ __launch_bounds__(256, 1) void k_l1(
    const float* __restrict__ obs, const float* __restrict__ act,
    const float* __restrict__ W01, const float* __restrict__ b01,
    const float* __restrict__ AB1)
{
    const int tid = threadIdx.x, lane = tid & 31, wid = tid >> 5;
    const int bx = blockIdx.x, b = blockIdx.y;
    __shared__ float Xs[7 * 128];      // [comp][c]
    __shared__ float sY[8][7];
    __shared__ float sBc[48], sBs[48];

    gdep_launch();   // let successors start their prologues now

    if (bx == 0 && b == 0) {
        int h = tid >> 2, k = tid & 3;
        g_sax[tid] = 1.4142135623730951f *
                     sinf((float)(k + 1) * PI_F * (float)h * (1.f / (NHC - 1)));
        if (tid < NPC) {
            float phi = (float)tid * (TWO_PI_F / NPC);
            float s1, c1v;
            sincosf(phi, &s1, &c1v);
            float c2v = c1v*c1v - s1*s1;
            float s2  = 2.f*s1*c1v;
            float c3v = c2v*c1v - s2*s1;
            float s3  = s2*c1v + c2v*s1;
            g_T1[tid] = make_float2(c1v, s1);
            g_T2[tid] = make_float2(c2v, s2);
            g_T3[tid] = make_float2(c3v, s3);
        }
    }

    const int o = bx * 8 + wid;

    const float* w0r = W01 + (size_t)o * (OBS_C + 1) + 4 * lane;
    float w0x = w0r[0], w0y = w0r[1], w0z = w0r[2], w0w = w0r[3];
    float4 wa[3], wb[3];
#pragma unroll
    for (int l = 0; l < 3; l++) {
        wa[l] = ((const float4*)AB1)[((size_t)(2*l)*256 + o)*32 + lane];
        wb[l] = ((const float4*)AB1)[((size_t)(2*l+1)*256 + o)*32 + lane];
    }

    const float* orow = obs + (size_t)b * (OBS_C * MC);
    for (int idx = tid; idx < OBS_C * MC; idx += 256) {
        int c = idx / 7, t = idx - c * 7;
        Xs[t * 128 + c] = orow[idx];
    }
    make_tables(tid, sBc, sBs);
    __syncthreads();

    const float4* Xs4 = (const float4*)Xs;
    {
        float acc[7];
#pragma unroll
        for (int m = 0; m < 7; m++) acc[m] = 0.f;
        float4 v0 = Xs4[lane];
        acc[0] += w0x*v0.x + w0y*v0.y + w0z*v0.z + w0w*v0.w;
#pragma unroll
        for (int l = 0; l < 3; l++) {
            float4 vc = Xs4[(1 + 2*l)*32 + lane];
            float4 vs = Xs4[(2 + 2*l)*32 + lane];
            CPLX4(acc[1+2*l], acc[2+2*l], wa[l], wb[l], vc, vs);
        }
#pragma unroll
        for (int off = 16; off > 0; off >>= 1)
#pragma unroll
            for (int m = 0; m < 7; m++)
                acc[m] += __shfl_xor_sync(0xffffffffu, acc[m], off);
        if (lane == 0)
#pragma unroll
            for (int m = 0; m < 7; m++) sY[wid][m] = acc[m];
    }
    __syncthreads();

    {
        const int a = tid >> 3, ol = tid & 7;
        const int oo = bx * 8 + ol;
        const int g = b * 32 + a;
        float y0 = sY[ol][0] + b01[oo] + W01[(size_t)oo * 129 + 128] * act[g];
        float yc[3], ys[3];
#pragma unroll
        for (int l = 0; l < 3; l++) { yc[l] = sY[ol][1+2*l]; ys[l] = sY[ol][2+2*l]; }
        float z0, zc[3], zs[3];
        felu(y0, yc, ys, sBc, sBs, z0, zc, zs);
        float* xo = g_X[0] + (size_t)g * XSTR;
        xo[oo] = z0;
#pragma unroll
        for (int l = 0; l < 3; l++) {
            xo[(1+2*l)*256 + oo] = zc[l];
            xo[(2+2*l)*256 + oo] = zs[l];
        }
    }
}

// ---------------- hidden layer: 2 CTA/SM, one wave, PDL-overlapped prologue ----
__global__ __launch_bounds__(256, 2) void k_hidden(
    const float* __restrict__ W0h, const float* __restrict__ b0h,
    const float* __restrict__ ABh, int layer, int inb)
{
    const int tid = threadIdx.x, lane = tid & 31, wid = tid >> 5;
    const int bx = blockIdx.x, gt = blockIdx.y;
    __shared__ __align__(16) float Xs[4 * XSTR];   // 28 KB
    __shared__ float sY[16][4][7];
    __shared__ float sBc[48], sBs[48];

    const float4* W04 = (const float4*)(W0h + (size_t)layer * 65536);
    const float4* AB4 = (const float4*)(ABh + (size_t)layer * 393216);
    const int oA = bx * 16 + wid * 2;
    const int oB = oA + 1;

    // independent prologue: j=0 weights + tables (overlaps predecessor via PDL)
    float4 w[14];
    {
        const int i4 = lane;
        w[0] = W04[(size_t)oA * 64 + i4];
        w[1] = W04[(size_t)oB * 64 + i4];
#pragma unroll
        for (int l = 0; l < 3; l++) {
            w[2 + 4*l + 0] = AB4[((size_t)(2*l)*256   + oA)*64 + i4];
            w[2 + 4*l + 1] = AB4[((size_t)(2*l+1)*256 + oA)*64 + i4];
            w[2 + 4*l + 2] = AB4[((size_t)(2*l)*256   + oB)*64 + i4];
            w[2 + 4*l + 3] = AB4[((size_t)(2*l+1)*256 + oB)*64 + i4];
        }
    }
    make_tables(tid, sBc, sBs);

    gdep_wait();     // predecessor's g_X writes now visible
    gdep_launch();

    {
        const float4* src = (const float4*)(g_X[inb] + (size_t)gt * 4 * XSTR);
        float4* dst = (float4*)Xs;
#pragma unroll
        for (int i = tid; i < 4 * XSTR / 4; i += 256) dst[i] = src[i];
    }
    __syncthreads();

    const float4* Xs4 = (const float4*)Xs;
    float acc[2][4][7];
#pragma unroll
    for (int t = 0; t < 2; t++)
#pragma unroll
        for (int g = 0; g < 4; g++)
#pragma unroll
            for (int m = 0; m < 7; m++) acc[t][g][m] = 0.f;

#pragma unroll 1
    for (int j = 0; j < 2; j++) {
        const int i4 = lane + 32 * j;
        if (j == 1) {
            w[0] = W04[(size_t)oA * 64 + i4];
            w[1] = W04[(size_t)oB * 64 + i4];
#pragma unroll
            for (int l = 0; l < 3; l++) {
                w[2 + 4*l + 0] = AB4[((size_t)(2*l)*256   + oA)*64 + i4];
                w[2 + 4*l + 1] = AB4[((size_t)(2*l+1)*256 + oA)*64 + i4];
                w[2 + 4*l + 2] = AB4[((size_t)(2*l)*256   + oB)*64 + i4];
                w[2 + 4*l + 3] = AB4[((size_t)(2*l+1)*256 + oB)*64 + i4];
            }
        }
#pragma unroll
        for (int g = 0; g < 4; g++) {
            const int base = g * (XSTR/4);
            float4 v0 = Xs4[base + i4];
            DOT4(acc[0][g][0], w[0], v0);
            DOT4(acc[1][g][0], w[1], v0);
#pragma unroll
            for (int l = 0; l < 3; l++) {
                float4 vc = Xs4[base + (1+2*l)*64 + i4];
                float4 vs = Xs4[base + (2+2*l)*64 + i4];
                CPLX4(acc[0][g][1+2*l], acc[0][g][2+2*l], w[2+4*l+0], w[2+4*l+1], vc, vs);
                CPLX4(acc[1][g][1+2*l], acc[1][g][2+2*l], w[2+4*l+2], w[2+4*l+3], vc, vs);
            }
        }
    }
#pragma unroll
    for (int off = 16; off > 0; off >>= 1)
#pragma unroll
        for (int t = 0; t < 2; t++)
#pragma unroll
            for (int g = 0; g < 4; g++)
#pragma unroll
                for (int m = 0; m < 7; m++)
                    acc[t][g][m] += __shfl_xor_sync(0xffffffffu, acc[t][g][m], off);
    if (lane == 0)
#pragma unroll
        for (int t = 0; t < 2; t++)
#pragma unroll
            for (int g = 0; g < 4; g++)
#pragma unroll
                for (int m = 0; m < 7; m++) sY[wid*2 + t][g][m] = acc[t][g][m];
    __syncthreads();

    if (tid < 64) {
        const int gl = tid >> 4, ol = tid & 15;
        const int o = bx * 16 + ol;
        const int g = gt * 4 + gl;
        float y0 = sY[ol][gl][0] + b0h[layer * 256 + o];
        float yc[3], ys[3];
#pragma unroll
        for (int l = 0; l < 3; l++) { yc[l] = sY[ol][gl][1+2*l]; ys[l] = sY[ol][gl][2+2*l]; }
        float z0, zc[3], zs[3];
        felu(y0, yc, ys, sBc, sBs, z0, zc, zs);
        float* xo = g_X[inb ^ 1] + (size_t)g * XSTR;
        xo[o] = z0;
#pragma unroll
        for (int l = 0; l < 3; l++) {
            xo[(1+2*l)*256 + o] = zc[l];
            xo[(2+2*l)*256 + o] = zs[l];
        }
    }
}

// ---------------- output layer: weights prefetched pre-wait --------------------
__global__ __launch_bounds__(256, 1) void k_out(
    const float* __restrict__ Wout, const float* __restrict__ bout,
    const float* __restrict__ ABout, int inb)
{
    const int tid = threadIdx.x, lane = tid & 31, wid = tid >> 5;
    const int g = blockIdx.x, half = blockIdx.y;
    const int o = half * 8 + wid;
    const float4* Xg = (const float4*)(g_X[inb] + (size_t)g * XSTR);

    // independent prologue: weights
    float4 w[2][7];
#pragma unroll
    for (int j = 0; j < 2; j++) {
        const int i4 = lane + 32 * j;
        w[j][0] = ((const float4*)Wout)[(size_t)o * 64 + i4];
#pragma unroll
        for (int l = 0; l < 3; l++) {
            w[j][1 + 2*l] = ((const float4*)ABout)[((size_t)(2*l)*16 + o)*64 + i4];
            w[j][2 + 2*l] = ((const float4*)ABout)[((size_t)(2*l+1)*16 + o)*64 + i4];
        }
    }

    gdep_wait();
    gdep_launch();

    float4 xv[2][7];
#pragma unroll
    for (int j = 0; j < 2; j++) {
        const int i4 = lane + 32 * j;
        xv[j][0] = Xg[i4];
#pragma unroll
        for (int l = 0; l < 3; l++) {
            xv[j][1 + 2*l] = Xg[(1+2*l)*64 + i4];
            xv[j][2 + 2*l] = Xg[(2+2*l)*64 + i4];
        }
    }

    float acc[7];
#pragma unroll
    for (int m = 0; m < 7; m++) acc[m] = 0.f;
#pragma unroll
    for (int j = 0; j < 2; j++) {
        DOT4(acc[0], w[j][0], xv[j][0]);
#pragma unroll
        for (int l = 0; l < 3; l++) {
            CPLX4(acc[1+2*l], acc[2+2*l], w[j][1+2*l], w[j][2+2*l], xv[j][1+2*l], xv[j][2+2*l]);
        }
    }
#pragma unroll
    for (int off = 16; off > 0; off >>= 1)
#pragma unroll
        for (int m = 0; m < 7; m++)
            acc[m] += __shfl_xor_sync(0xffffffffu, acc[m], off);
    if (lane == 0) {
        float* dst = g_coef + ((size_t)g * 16 + o) * MC;
        dst[0] = acc[0] + bout[o];
#pragma unroll
        for (int m = 1; m < 7; m++) dst[m] = acc[m];
    }
}

// ---------------- expansion kernel: table-driven prologue, __stcs stores -------
__global__ __launch_bounds__(256) void k_expand(
    const float* __restrict__ rad, float* __restrict__ out)
{
    const int gr = blockIdx.x;          // g*NR + r
    const int tid = threadIdx.x;
    __shared__ float sc1[28];
    __shared__ float su[NPC * 4];       // [p][k] -> float4 per p

    gdep_wait();   // all reads below depend on earlier kernels

    if (tid < 28) {
        const int g = gr >> 6, r = gr & 63;
        const int k = tid / 7, m = tid - 7 * k;
        const float* cf = g_coef + (size_t)g * 112;
        float s = 0.f;
#pragma unroll
        for (int n = 0; n < 4; n++)
            s += cf[(n*4 + k)*7 + m] * rad[(m*4 + n) * NRC + r];
        sc1[tid] = s;
    }

    const int hgrp = tid & 15;
    float4 axj[4];
#pragma unroll
    for (int j = 0; j < 4; j++)
        axj[j] = ((const float4*)g_sax)[hgrp * 4 + j];
    __syncthreads();

    const float A0 = 0.3989422804014327f;   // 1/sqrt(2*pi)
    const float ISP = 0.5641895835477563f;  // 1/sqrt(pi)
#pragma unroll
    for (int idx = tid; idx < 512; idx += 256) {
        int k = idx >> 7, p = idx & 127;
        float2 t1 = g_T1[p], t2 = g_T2[p], t3 = g_T3[p];
        const float* c = sc1 + k * MC;
        su[p * 4 + k] = c[0]*A0 + ISP*(c[1]*t1.x + c[2]*t1.y +
                                       c[3]*t2.x + c[4]*t2.y +
                                       c[5]*t3.x + c[6]*t3.y);
    }
    __syncthreads();

    const float4* su4 = (const float4*)su;
    float4* ob = (float4*)out + (size_t)gr * (NPC * NHC / 4);
    const int pg = tid >> 4;
#pragma unroll
    for (int it = 0; it < 8; it++) {
        int p = it * 16 + pg;
        float4 u = su4[p];
        float4 v;
        v.x = u.x*axj[0].x + u.y*axj[0].y + u.z*axj[0].z + u.w*axj[0].w;
        v.y = u.x*axj[1].x + u.y*axj[1].y + u.z*axj[1].z + u.w*axj[1].w;
        v.z = u.x*axj[2].x + u.y*axj[2].y + u.z*axj[2].z + u.w*axj[2].w;
        v.w = u.x*axj[3].x + u.y*axj[3].y + u.z*axj[3].z + u.w*axj[3].w;
        __stcs(&ob[p * 16 + hgrp], v);
    }
}

// ---------------- launch (PDL-chained) ----------------
static void launch_k(const void* fn, dim3 grid, dim3 block, void** args, bool pdl)
{
    cudaLaunchConfig_t cfg = {};
    cfg.gridDim = grid;
    cfg.blockDim = block;
    cfg.stream = 0;
    cudaLaunchAttribute attr[1];
    if (pdl) {
        attr[0].id = cudaLaunchAttributeProgrammaticStreamSerialization;
        attr[0].val.programmaticStreamSerializationAllowed = 1;
        cfg.attrs = attr;
        cfg.numAttrs = 1;
    }
    cudaLaunchKernelExC(&cfg, fn, args);
}

extern "C" void kernel_launch(void* const* d_in, const int* in_sizes, int n_in,
                              void* d_out, int out_size)
{
    const float* obs   = (const float*)d_in[0];
    const float* act   = (const float*)d_in[1];
    const float* W0_1  = (const float*)d_in[2];
    const float* b0_1  = (const float*)d_in[3];
    const float* AB1   = (const float*)d_in[4];
    const float* W0_h  = (const float*)d_in[5];
    const float* b0_h  = (const float*)d_in[6];
    const float* ABh   = (const float*)d_in[7];
    const float* Wout0 = (const float*)d_in[8];
    const float* bout0 = (const float*)d_in[9];
    const float* ABout = (const float*)d_in[10];
    const float* rad   = (const float*)d_in[11];
    float* outp = (float*)d_out;

    int layer0 = 0, layer1 = 1, inb0 = 0, inb1 = 1, inbo = 0;

    {
        void* a[] = {&obs, &act, &W0_1, &b0_1, &AB1};
        launch_k((const void*)k_l1, dim3(32, 2), dim3(256), a, false);
    }
    {
        void* a[] = {&W0_h, &b0_h, &ABh, &layer0, &inb0};
        launch_k((const void*)k_hidden, dim3(16, 16), dim3(256), a, true);
    }
    {
        void* a[] = {&W0_h, &b0_h, &ABh, &layer1, &inb1};
        launch_k((const void*)k_hidden, dim3(16, 16), dim3(256), a, true);
    }
    {
        void* a[] = {&Wout0, &bout0, &ABout, &inbo};
        launch_k((const void*)k_out, dim3(64, 2), dim3(256), a, true);
    }
    {
        void* a[] = {&rad, &outp};
        launch_k((const void*)k_expand, dim3(GC * NRC), dim3(256), a, true);
    }
}